// round 1
// baseline (speedup 1.0000x reference)
#include <cuda_runtime.h>
#include <math.h>

#define BT 8
#define NQ 1024
#define DM 512
#define HEADS 8
#define HD 64
#define TOT (BT*NQ*DM)

// Scratch (allocation-free rule: __device__ globals)
__device__ float g_Qp[TOT];
__device__ float g_Kp[TOT];
__device__ float g_Vp[TOT];
__device__ float g_O [TOT];
__device__ float g_T [TOT];
__device__ float g_U [TOT];

// ---------------------------------------------------------------------------
// GEMM: C[M=8192,512] = A[M,512] @ W[512,512] (+bias); MODE 1 adds
// residual + relu: C = R + relu(acc + bias)
// Block tile 64x64, BK=16, 256 threads, 4x4 per-thread microtile.
// ---------------------------------------------------------------------------
template <int MODE>
__global__ __launch_bounds__(256) void gemm512(
    const float* __restrict__ A, const float* __restrict__ W,
    const float* __restrict__ bias, const float* __restrict__ R,
    float* __restrict__ C)
{
    __shared__ float As[16][64];   // [k][m]
    __shared__ float Bs[16][64];   // [k][n]

    const int tid = threadIdx.x;
    const int bm = blockIdx.y * 64;
    const int bn = blockIdx.x * 64;
    const int tx = tid & 15, ty = tid >> 4;

    const int arow = tid >> 2;            // 0..63
    const int acol = (tid & 3) << 2;      // 0,4,8,12
    const int brow = tid >> 4;            // 0..15
    const int bcol = (tid & 15) << 2;     // 0..60

    const float* Ap = A + (size_t)(bm + arow) * DM + acol;
    const float* Wp = W + (size_t)brow * DM + bn + bcol;

    float acc[4][4] = {};

    for (int k0 = 0; k0 < DM; k0 += 16) {
        float4 av = *(const float4*)(Ap + k0);
        float4 bv = *(const float4*)(Wp + (size_t)k0 * DM);
        As[acol + 0][arow] = av.x;
        As[acol + 1][arow] = av.y;
        As[acol + 2][arow] = av.z;
        As[acol + 3][arow] = av.w;
        *(float4*)&Bs[brow][bcol] = bv;
        __syncthreads();
#pragma unroll
        for (int k = 0; k < 16; ++k) {
            float4 a4 = *(const float4*)&As[k][ty << 2];
            float4 b4 = *(const float4*)&Bs[k][tx << 2];
            float af[4] = {a4.x, a4.y, a4.z, a4.w};
            float bf[4] = {b4.x, b4.y, b4.z, b4.w};
#pragma unroll
            for (int i = 0; i < 4; ++i)
#pragma unroll
                for (int j = 0; j < 4; ++j)
                    acc[i][j] = fmaf(af[i], bf[j], acc[i][j]);
        }
        __syncthreads();
    }

    float4 bia = *(const float4*)(bias + bn + (tx << 2));
#pragma unroll
    for (int i = 0; i < 4; ++i) {
        size_t off = (size_t)(bm + (ty << 2) + i) * DM + bn + (tx << 2);
        float4 o;
        o.x = acc[i][0] + bia.x;
        o.y = acc[i][1] + bia.y;
        o.z = acc[i][2] + bia.z;
        o.w = acc[i][3] + bia.w;
        if (MODE == 1) {
            float4 r = *(const float4*)(R + off);
            o.x = r.x + fmaxf(o.x, 0.f);
            o.y = r.y + fmaxf(o.y, 0.f);
            o.z = r.z + fmaxf(o.z, 0.f);
            o.w = r.w + fmaxf(o.w, 0.f);
        }
        *(float4*)(C + off) = o;
    }
}

// ---------------------------------------------------------------------------
// Attention: per block = (64 q-rows, head h, batch b). Flash-style over 16
// key tiles of 64. Fused residual += projected-Q (Q tile stays in smem).
// ---------------------------------------------------------------------------
__global__ __launch_bounds__(256) void attn_kernel(
    const float* __restrict__ Qp, const float* __restrict__ Kp,
    const float* __restrict__ Vp, float* __restrict__ O)
{
    __shared__ float Qs[64][64];   // [d][q]  (transposed)
    __shared__ float Ks[64][64];   // [d][k]  -> reused as P[k][q]
    __shared__ float Vs[64][64];   // [k][d]

    const int b = blockIdx.z, h = blockIdx.y, q0 = blockIdx.x * 64;
    const int tid = threadIdx.x;
    const int tx = tid & 15, ty = tid >> 4;

    const float* Qb = Qp + ((size_t)(b * NQ) + q0) * DM + h * HD;
    const float* Kb = Kp + (size_t)(b * NQ) * DM + h * HD;
    const float* Vb = Vp + (size_t)(b * NQ) * DM + h * HD;

    const int lr = tid >> 2;            // 0..63 row
    const int lc = (tid & 3) << 4;      // 0,16,32,48 col base

    // Load Q tile (transposed into Qs[d][q])
#pragma unroll
    for (int i = 0; i < 4; ++i) {
        float4 v = *(const float4*)(Qb + (size_t)lr * DM + lc + i * 4);
        Qs[lc + i * 4 + 0][lr] = v.x;
        Qs[lc + i * 4 + 1][lr] = v.y;
        Qs[lc + i * 4 + 2][lr] = v.z;
        Qs[lc + i * 4 + 3][lr] = v.w;
    }

    float m_i[4], l_i[4], acc_o[4][4];
#pragma unroll
    for (int i = 0; i < 4; ++i) {
        m_i[i] = -1e30f;
        l_i[i] = 0.f;
#pragma unroll
        for (int j = 0; j < 4; ++j) acc_o[i][j] = 0.f;
    }

    for (int kt = 0; kt < NQ; kt += 64) {
        __syncthreads();   // Q visible (1st iter) / prev P,V reads done
        // Load K (transposed) and V (natural)
#pragma unroll
        for (int i = 0; i < 4; ++i) {
            float4 kv = *(const float4*)(Kb + (size_t)(kt + lr) * DM + lc + i * 4);
            Ks[lc + i * 4 + 0][lr] = kv.x;
            Ks[lc + i * 4 + 1][lr] = kv.y;
            Ks[lc + i * 4 + 2][lr] = kv.z;
            Ks[lc + i * 4 + 3][lr] = kv.w;
            float4 vv = *(const float4*)(Vb + (size_t)(kt + lr) * DM + lc + i * 4);
            *(float4*)&Vs[lr][lc + i * 4] = vv;
        }
        __syncthreads();

        // S = Q @ K^T (64x64x64)
        float s[4][4] = {};
#pragma unroll
        for (int d = 0; d < 64; ++d) {
            float4 a4 = *(const float4*)&Qs[d][ty << 2];
            float4 b4 = *(const float4*)&Ks[d][tx << 2];
            float af[4] = {a4.x, a4.y, a4.z, a4.w};
            float bf[4] = {b4.x, b4.y, b4.z, b4.w};
#pragma unroll
            for (int i = 0; i < 4; ++i)
#pragma unroll
                for (int j = 0; j < 4; ++j)
                    s[i][j] = fmaf(af[i], bf[j], s[i][j]);
        }

        // Online softmax per q-row (row = threads sharing ty; 16-lane shfl group)
#pragma unroll
        for (int i = 0; i < 4; ++i) {
#pragma unroll
            for (int j = 0; j < 4; ++j) s[i][j] *= 0.125f;  // 1/sqrt(64)
            float rm = fmaxf(fmaxf(s[i][0], s[i][1]), fmaxf(s[i][2], s[i][3]));
            rm = fmaxf(rm, __shfl_xor_sync(0xffffffffu, rm, 1));
            rm = fmaxf(rm, __shfl_xor_sync(0xffffffffu, rm, 2));
            rm = fmaxf(rm, __shfl_xor_sync(0xffffffffu, rm, 4));
            rm = fmaxf(rm, __shfl_xor_sync(0xffffffffu, rm, 8));
            float mn = fmaxf(m_i[i], rm);
            float alpha = __expf(m_i[i] - mn);
            float rs = 0.f;
#pragma unroll
            for (int j = 0; j < 4; ++j) {
                s[i][j] = __expf(s[i][j] - mn);
                rs += s[i][j];
            }
            rs += __shfl_xor_sync(0xffffffffu, rs, 1);
            rs += __shfl_xor_sync(0xffffffffu, rs, 2);
            rs += __shfl_xor_sync(0xffffffffu, rs, 4);
            rs += __shfl_xor_sync(0xffffffffu, rs, 8);
            l_i[i] = l_i[i] * alpha + rs;
            m_i[i] = mn;
#pragma unroll
            for (int j = 0; j < 4; ++j) acc_o[i][j] *= alpha;
        }

        __syncthreads();   // everyone done reading Ks as K
        // Write P transposed into Ks: P[k][q]
#pragma unroll
        for (int i = 0; i < 4; ++i)
#pragma unroll
            for (int j = 0; j < 4; ++j)
                Ks[(tx << 2) + j][(ty << 2) + i] = s[i][j];
        __syncthreads();

        // O += P @ V (64x64x64)
#pragma unroll
        for (int k = 0; k < 64; ++k) {
            float4 a4 = *(const float4*)&Ks[k][ty << 2];   // P[k][q..]
            float4 b4 = *(const float4*)&Vs[k][tx << 2];   // V[k][d..]
            float af[4] = {a4.x, a4.y, a4.z, a4.w};
            float bf[4] = {b4.x, b4.y, b4.z, b4.w};
#pragma unroll
            for (int i = 0; i < 4; ++i)
#pragma unroll
                for (int j = 0; j < 4; ++j)
                    acc_o[i][j] = fmaf(af[i], bf[j], acc_o[i][j]);
        }
    }

    // Epilogue: normalize + Q residual (Qs still holds the Q tile)
#pragma unroll
    for (int i = 0; i < 4; ++i) {
        float inv = 1.f / l_i[i];
#pragma unroll
        for (int j = 0; j < 4; ++j) {
            int q = (ty << 2) + i;
            int dcol = (tx << 2) + j;
            float val = acc_o[i][j] * inv + Qs[dcol][q];
            O[((size_t)(b * NQ) + q0 + q) * DM + h * HD + dcol] = val;
        }
    }
}

// ---------------------------------------------------------------------------
// LayerNorm over last dim (512). One warp per row; 8 rows per 256-thread block.
// ---------------------------------------------------------------------------
__global__ __launch_bounds__(256) void ln_kernel(
    const float* __restrict__ X, const float* __restrict__ gam,
    const float* __restrict__ bet, float* __restrict__ Y)
{
    const int row = blockIdx.x * 8 + (threadIdx.x >> 5);
    const int lane = threadIdx.x & 31;
    const float* x = X + (size_t)row * DM;

    float v[16];
    float s = 0.f, ss = 0.f;
#pragma unroll
    for (int i = 0; i < 4; ++i) {
        float4 t = *(const float4*)(x + i * 128 + lane * 4);
        v[i * 4 + 0] = t.x; v[i * 4 + 1] = t.y;
        v[i * 4 + 2] = t.z; v[i * 4 + 3] = t.w;
        s += t.x + t.y + t.z + t.w;
        ss += t.x * t.x + t.y * t.y + t.z * t.z + t.w * t.w;
    }
#pragma unroll
    for (int m = 16; m >= 1; m >>= 1) {
        s += __shfl_xor_sync(0xffffffffu, s, m);
        ss += __shfl_xor_sync(0xffffffffu, ss, m);
    }
    const float mean = s * (1.f / DM);
    const float var = ss * (1.f / DM) - mean * mean;
    const float inv = rsqrtf(var + 1e-5f);

    float* y = Y + (size_t)row * DM;
#pragma unroll
    for (int i = 0; i < 4; ++i) {
        int col = i * 128 + lane * 4;
        float4 g = *(const float4*)(gam + col);
        float4 bb = *(const float4*)(bet + col);
        float4 o;
        o.x = (v[i * 4 + 0] - mean) * inv * g.x + bb.x;
        o.y = (v[i * 4 + 1] - mean) * inv * g.y + bb.y;
        o.z = (v[i * 4 + 2] - mean) * inv * g.z + bb.z;
        o.w = (v[i * 4 + 3] - mean) * inv * g.w + bb.w;
        *(float4*)(y + col) = o;
    }
}

// ---------------------------------------------------------------------------
extern "C" void kernel_launch(void* const* d_in, const int* in_sizes, int n_in,
                              void* d_out, int out_size)
{
    const float* Q  = (const float*)d_in[0];
    const float* K  = (const float*)d_in[1];
    const float* Wq = (const float*)d_in[2];
    const float* bq = (const float*)d_in[3];
    const float* Wk = (const float*)d_in[4];
    const float* bk = (const float*)d_in[5];
    const float* Wv = (const float*)d_in[6];
    const float* bv = (const float*)d_in[7];
    const float* Wo = (const float*)d_in[8];
    const float* bo = (const float*)d_in[9];
    const float* g0 = (const float*)d_in[10];
    const float* b0 = (const float*)d_in[11];
    const float* g1 = (const float*)d_in[12];
    const float* b1 = (const float*)d_in[13];
    float* out = (float*)d_out;

    float *Qp, *Kp, *Vp, *O, *T, *U;
    cudaGetSymbolAddress((void**)&Qp, g_Qp);
    cudaGetSymbolAddress((void**)&Kp, g_Kp);
    cudaGetSymbolAddress((void**)&Vp, g_Vp);
    cudaGetSymbolAddress((void**)&O,  g_O);
    cudaGetSymbolAddress((void**)&T,  g_T);
    cudaGetSymbolAddress((void**)&U,  g_U);

    dim3 gemmGrid(DM / 64, (BT * NQ) / 64);   // (8, 128)

    // Projections
    gemm512<0><<<gemmGrid, 256>>>(Q, Wq, bq, nullptr, Qp);
    gemm512<0><<<gemmGrid, 256>>>(K, Wk, bk, nullptr, Kp);
    gemm512<0><<<gemmGrid, 256>>>(K, Wv, bv, nullptr, Vp);

    // Attention + Q residual
    attn_kernel<<<dim3(NQ / 64, HEADS, BT), 256>>>(Qp, Kp, Vp, O);

    // LN0
    ln_kernel<<<(BT * NQ) / 8, 256>>>(O, g0, b0, T);

    // U = T + relu(T @ Wo + bo)
    gemm512<1><<<gemmGrid, 256>>>(T, Wo, bo, T, U);

    // LN1 -> out
    ln_kernel<<<(BT * NQ) / 8, 256>>>(U, g1, b1, out);
}

// round 3
// speedup vs baseline: 1.7457x; 1.7457x over previous
#include <cuda_runtime.h>
#include <cuda_bf16.h>
#include <math.h>
#include <stdint.h>

#define BT 8
#define NQ 1024
#define DM 512
#define HEADS 8
#define HD 64
#define TOT (BT*NQ*DM)

// fp32 scratch
__device__ float g_Qp[TOT];
__device__ float g_Kp[TOT];
__device__ float g_Vp[TOT];
__device__ float g_O [TOT];
__device__ float g_T [TOT];
__device__ float g_U [TOT];
// bf16 split scratch
__device__ __nv_bfloat16 g_Ah[TOT], g_Al[TOT];     // activation A (Q, then T)
__device__ __nv_bfloat16 g_Kbh[TOT], g_Kbl[TOT];   // activation K
__device__ __nv_bfloat16 g_Wth[4][DM*DM], g_Wtl[4][DM*DM]; // transposed weights

// ===========================================================================
// Helpers
// ===========================================================================
__device__ __forceinline__ uint32_t smem_u32(const void* p) {
    uint32_t a;
    asm("{ .reg .u64 t; cvta.to.shared.u64 t, %1; cvt.u32.u64 %0, t; }"
        : "=r"(a) : "l"(p));
    return a;
}

__device__ __forceinline__ void ldsm4(uint32_t r[4], uint32_t addr) {
    asm volatile("ldmatrix.sync.aligned.m8n8.x4.shared.b16 {%0,%1,%2,%3}, [%4];"
        : "=r"(r[0]), "=r"(r[1]), "=r"(r[2]), "=r"(r[3]) : "r"(addr));
}

__device__ __forceinline__ void mma16816(float c[4], const uint32_t a[4],
                                         uint32_t b0, uint32_t b1) {
    asm volatile(
        "mma.sync.aligned.m16n8k16.row.col.f32.bf16.bf16.f32 "
        "{%0,%1,%2,%3}, {%4,%5,%6,%7}, {%8,%9}, {%0,%1,%2,%3};"
        : "+f"(c[0]), "+f"(c[1]), "+f"(c[2]), "+f"(c[3])
        : "r"(a[0]), "r"(a[1]), "r"(a[2]), "r"(a[3]), "r"(b0), "r"(b1));
}

__device__ __forceinline__ uint32_t packbf(float x, float y) {
    __nv_bfloat162 h = __floats2bfloat162_rn(x, y);
    return *reinterpret_cast<uint32_t*>(&h);
}

__device__ __forceinline__ void split_pair(float x, float y,
                                           uint32_t& hi, uint32_t& lo) {
    __nv_bfloat162 h = __floats2bfloat162_rn(x, y);
    float rx = x - __bfloat162float(h.x);
    float ry = y - __bfloat162float(h.y);
    hi = *reinterpret_cast<uint32_t*>(&h);
    lo = packbf(rx, ry);
}

// ===========================================================================
// Split-convert: fp32 -> bf16 hi/lo
// ===========================================================================
__global__ __launch_bounds__(256) void cvt_split(
    const float4* __restrict__ X, __nv_bfloat16* __restrict__ Xh,
    __nv_bfloat16* __restrict__ Xl, int n4)
{
    for (int i = blockIdx.x * blockDim.x + threadIdx.x; i < n4;
         i += gridDim.x * blockDim.x) {
        float4 v = X[i];
        uint32_t h0, l0, h1, l1;
        split_pair(v.x, v.y, h0, l0);
        split_pair(v.z, v.w, h1, l1);
        *(uint2*)&Xh[4 * i] = make_uint2(h0, h1);
        *(uint2*)&Xl[4 * i] = make_uint2(l0, l1);
    }
}

// Weight transpose + split: W[k][n] -> Wt[n][k] bf16 hi/lo
__global__ __launch_bounds__(256) void cvt_wt(
    const float* __restrict__ W, __nv_bfloat16* __restrict__ Wth,
    __nv_bfloat16* __restrict__ Wtl)
{
    __shared__ float tile[32][33];
    const int tx = threadIdx.x, ty = threadIdx.y;  // 32 x 8
    const int kb = blockIdx.y * 32, nb = blockIdx.x * 32;
#pragma unroll
    for (int i = 0; i < 32; i += 8)
        tile[ty + i][tx] = W[(size_t)(kb + ty + i) * DM + nb + tx];
    __syncthreads();
#pragma unroll
    for (int i = 0; i < 32; i += 8) {
        float v = tile[tx][ty + i];
        __nv_bfloat16 h = __float2bfloat16(v);
        size_t o = (size_t)(nb + ty + i) * DM + kb + tx;
        Wth[o] = h;
        Wtl[o] = __float2bfloat16(v - __bfloat162float(h));
    }
}

// ===========================================================================
// mma.sync GEMM: C[8192,512] = A[8192,512] @ W + bias   (MODE1: +relu+resid)
// A given as bf16 hi/lo [m][k]; W given as transposed bf16 hi/lo Bt[n][k].
// CTA 128x128, 8 warps (warp tile 32x64), K-chunk 32.
// ===========================================================================
#define GLD 40   // smem row stride (bf16 elems) - conflict-free for ldsm

template <int MODE>
__global__ __launch_bounds__(256) void gemm_mma(
    const __nv_bfloat16* __restrict__ Ah, const __nv_bfloat16* __restrict__ Al,
    const __nv_bfloat16* __restrict__ Bh, const __nv_bfloat16* __restrict__ Bl,
    const float* __restrict__ bias, const float* __restrict__ R,
    float* __restrict__ C)
{
    __shared__ __nv_bfloat16 sAh[128 * GLD], sAl[128 * GLD];
    __shared__ __nv_bfloat16 sBh[128 * GLD], sBl[128 * GLD];

    const int tid = threadIdx.x, wid = tid >> 5, lane = tid & 31;
    const int g = lane >> 2, t = lane & 3;
    const int lrow = lane & 15, lhalf = (lane >> 4) << 3;
    const int bm = blockIdx.y * 128, bn = blockIdx.x * 128;
    const int wm = (wid & 3) * 32, wn = (wid >> 2) * 64;

    const uint32_t uAh = smem_u32(sAh), uAl = smem_u32(sAl);
    const uint32_t uBh = smem_u32(sBh), uBl = smem_u32(sBl);

    const int r = tid >> 1, sgc = (tid & 1) * 16;

    float acc[2][8][4] = {};

    for (int k0 = 0; k0 < DM; k0 += 32) {
        __syncthreads();
#pragma unroll
        for (int c = 0; c < 4; ++c) {
            int col = sgc + c * 4;
            *(uint2*)&sAh[r * GLD + col] = *(const uint2*)&Ah[(size_t)(bm + r) * DM + k0 + col];
            *(uint2*)&sAl[r * GLD + col] = *(const uint2*)&Al[(size_t)(bm + r) * DM + k0 + col];
            *(uint2*)&sBh[r * GLD + col] = *(const uint2*)&Bh[(size_t)(bn + r) * DM + k0 + col];
            *(uint2*)&sBl[r * GLD + col] = *(const uint2*)&Bl[(size_t)(bn + r) * DM + k0 + col];
        }
        __syncthreads();

#pragma unroll
        for (int kb = 0; kb < 2; ++kb) {
            const uint32_t cofs = (uint32_t)(lhalf + kb * 16) * 2;
            uint32_t ah[2][4], al[2][4];
#pragma unroll
            for (int mf = 0; mf < 2; ++mf) {
                uint32_t rofs = (uint32_t)((wm + mf * 16 + lrow) * GLD) * 2 + cofs;
                ldsm4(ah[mf], uAh + rofs);
                ldsm4(al[mf], uAl + rofs);
            }
#pragma unroll
            for (int j = 0; j < 4; ++j) {
                uint32_t bhf[4], blf[4];
                uint32_t rofs = (uint32_t)((wn + j * 16 + lrow) * GLD) * 2 + cofs;
                ldsm4(bhf, uBh + rofs);
                ldsm4(blf, uBl + rofs);
#pragma unroll
                for (int mf = 0; mf < 2; ++mf) {
                    mma16816(acc[mf][2 * j],     ah[mf], bhf[0], bhf[2]);
                    mma16816(acc[mf][2 * j + 1], ah[mf], bhf[1], bhf[3]);
                    mma16816(acc[mf][2 * j],     ah[mf], blf[0], blf[2]);
                    mma16816(acc[mf][2 * j + 1], ah[mf], blf[1], blf[3]);
                    mma16816(acc[mf][2 * j],     al[mf], bhf[0], bhf[2]);
                    mma16816(acc[mf][2 * j + 1], al[mf], bhf[1], bhf[3]);
                }
            }
        }
    }

    // Epilogue
#pragma unroll
    for (int mf = 0; mf < 2; ++mf) {
#pragma unroll
        for (int nf = 0; nf < 8; ++nf) {
            const int row0 = bm + wm + mf * 16 + g;
            const int col = bn + wn + nf * 8 + 2 * t;
            float2 bv = *(const float2*)&bias[col];
            float v0 = acc[mf][nf][0] + bv.x, v1 = acc[mf][nf][1] + bv.y;
            float v2 = acc[mf][nf][2] + bv.x, v3 = acc[mf][nf][3] + bv.y;
            size_t o0 = (size_t)row0 * DM + col;
            size_t o1 = (size_t)(row0 + 8) * DM + col;
            if (MODE == 1) {
                float2 r0 = *(const float2*)&R[o0];
                float2 r1 = *(const float2*)&R[o1];
                v0 = r0.x + fmaxf(v0, 0.f); v1 = r0.y + fmaxf(v1, 0.f);
                v2 = r1.x + fmaxf(v2, 0.f); v3 = r1.y + fmaxf(v3, 0.f);
            }
            *(float2*)&C[o0] = make_float2(v0, v1);
            *(float2*)&C[o1] = make_float2(v2, v3);
        }
    }
}

// ===========================================================================
// Attention (FA2-style, mma.sync): CTA = 128 q-rows x (head, batch).
// Q/K smem [row][64] pad 72; V transposed smem [d][key] pad 136. All bf16 hi/lo.
// Warp tile: m16 x n128 for S; m16 x n64 for O. Softmax in registers.
// ===========================================================================
#define QKLD 72
#define VLD  136
#define A_QH 0
#define A_QL 18432
#define A_KH 36864
#define A_KL 55296
#define A_VH 73728
#define A_VL 91136
#define A_TOTAL 108544

__global__ __launch_bounds__(256) void attn_mma(
    const float* __restrict__ Qp, const float* __restrict__ Kp,
    const float* __restrict__ Vp, float* __restrict__ O)
{
    extern __shared__ char sm[];
    const uint32_t sb = smem_u32(sm);
    const int tid = threadIdx.x, wid = tid >> 5, lane = tid & 31;
    const int g = lane >> 2, t = lane & 3;
    const int lrow = lane & 15, lhalf = (lane >> 4) << 3;
    const int b = blockIdx.z, h = blockIdx.y, q0 = blockIdx.x * 128;

    const float* Qg = Qp + ((size_t)(b * NQ) + q0) * DM + h * HD;
    const float* Kg = Kp + (size_t)(b * NQ) * DM + h * HD;
    const float* Vg = Vp + (size_t)(b * NQ) * DM + h * HD;

    // ---- load Q tile (128 x 64) as bf16 hi/lo ----
    for (int idx = tid; idx < 128 * 16; idx += 256) {
        int row = idx >> 4, c4 = (idx & 15) * 4;
        float4 v = *(const float4*)(Qg + (size_t)row * DM + c4);
        uint32_t h0, l0, h1, l1;
        split_pair(v.x, v.y, h0, l0);
        split_pair(v.z, v.w, h1, l1);
        int e = (row * QKLD + c4) * 2;
        *(uint32_t*)(sm + A_QH + e) = h0;
        *(uint32_t*)(sm + A_QH + e + 4) = h1;
        *(uint32_t*)(sm + A_QL + e) = l0;
        *(uint32_t*)(sm + A_QL + e + 4) = l1;
    }

    float m0 = -1e30f, m1 = -1e30f, l0 = 0.f, l1 = 0.f;
    float oacc[8][4] = {};
    float s[16][4];

    for (int kc = 0; kc < 8; ++kc) {
        __syncthreads();
        // ---- load K chunk + V chunk (transposed) ----
        for (int idx = tid; idx < 128 * 16; idx += 256) {
            int row = idx >> 4, c4 = (idx & 15) * 4;
            const size_t gofs = (size_t)(kc * 128 + row) * DM + c4;
            float4 v = *(const float4*)(Kg + gofs);
            uint32_t h0, lo0, h1, lo1;
            split_pair(v.x, v.y, h0, lo0);
            split_pair(v.z, v.w, h1, lo1);
            int e = (row * QKLD + c4) * 2;
            *(uint32_t*)(sm + A_KH + e) = h0;
            *(uint32_t*)(sm + A_KH + e + 4) = h1;
            *(uint32_t*)(sm + A_KL + e) = lo0;
            *(uint32_t*)(sm + A_KL + e + 4) = lo1;

            float4 w = *(const float4*)(Vg + gofs);
            float wv[4] = {w.x, w.y, w.z, w.w};
#pragma unroll
            for (int e2 = 0; e2 < 4; ++e2) {
                __nv_bfloat16 hh = __float2bfloat16(wv[e2]);
                float rr = wv[e2] - __bfloat162float(hh);
                int vo = ((c4 + e2) * VLD + row) * 2;
                *(__nv_bfloat16*)(sm + A_VH + vo) = hh;
                *(__nv_bfloat16*)(sm + A_VL + vo) = __float2bfloat16(rr);
            }
        }
        __syncthreads();

        // ---- S = Q K^T  (m16 x n128 x k64 per warp) ----
#pragma unroll
        for (int nf = 0; nf < 16; ++nf)
#pragma unroll
            for (int e = 0; e < 4; ++e) s[nf][e] = 0.f;

#pragma unroll
        for (int kb = 0; kb < 4; ++kb) {
            const uint32_t cofs = (uint32_t)(lhalf + kb * 16) * 2;
            uint32_t aqh[4], aql[4];
            uint32_t qro = (uint32_t)((wid * 16 + lrow) * QKLD) * 2 + cofs;
            ldsm4(aqh, sb + A_QH + qro);
            ldsm4(aql, sb + A_QL + qro);
#pragma unroll
            for (int j = 0; j < 8; ++j) {
                uint32_t bh[4], bl[4];
                uint32_t kro = (uint32_t)((j * 16 + lrow) * QKLD) * 2 + cofs;
                ldsm4(bh, sb + A_KH + kro);
                ldsm4(bl, sb + A_KL + kro);
                mma16816(s[2 * j],     aqh, bh[0], bh[2]);
                mma16816(s[2 * j + 1], aqh, bh[1], bh[3]);
                mma16816(s[2 * j],     aqh, bl[0], bl[2]);
                mma16816(s[2 * j + 1], aqh, bl[1], bl[3]);
                mma16816(s[2 * j],     aql, bh[0], bh[2]);
                mma16816(s[2 * j + 1], aql, bh[1], bh[3]);
            }
        }

        // ---- online softmax (rows g and g+8; 4-lane groups) ----
        const float scale = 0.125f;
        float rm0 = -1e30f, rm1 = -1e30f;
#pragma unroll
        for (int nf = 0; nf < 16; ++nf) {
            rm0 = fmaxf(rm0, fmaxf(s[nf][0], s[nf][1]));
            rm1 = fmaxf(rm1, fmaxf(s[nf][2], s[nf][3]));
        }
        rm0 = fmaxf(rm0, __shfl_xor_sync(0xffffffffu, rm0, 1));
        rm0 = fmaxf(rm0, __shfl_xor_sync(0xffffffffu, rm0, 2));
        rm1 = fmaxf(rm1, __shfl_xor_sync(0xffffffffu, rm1, 1));
        rm1 = fmaxf(rm1, __shfl_xor_sync(0xffffffffu, rm1, 2));
        float mn0 = fmaxf(m0, rm0 * scale);
        float mn1 = fmaxf(m1, rm1 * scale);
        float al0 = __expf(m0 - mn0);
        float al1 = __expf(m1 - mn1);
        float sum0 = 0.f, sum1 = 0.f;
#pragma unroll
        for (int nf = 0; nf < 16; ++nf) {
            s[nf][0] = __expf(fmaf(s[nf][0], scale, -mn0));
            s[nf][1] = __expf(fmaf(s[nf][1], scale, -mn0));
            s[nf][2] = __expf(fmaf(s[nf][2], scale, -mn1));
            s[nf][3] = __expf(fmaf(s[nf][3], scale, -mn1));
            sum0 += s[nf][0] + s[nf][1];
            sum1 += s[nf][2] + s[nf][3];
        }
        sum0 += __shfl_xor_sync(0xffffffffu, sum0, 1);
        sum0 += __shfl_xor_sync(0xffffffffu, sum0, 2);
        sum1 += __shfl_xor_sync(0xffffffffu, sum1, 1);
        sum1 += __shfl_xor_sync(0xffffffffu, sum1, 2);
        l0 = l0 * al0 + sum0;
        l1 = l1 * al1 + sum1;
        m0 = mn0; m1 = mn1;
#pragma unroll
        for (int nf = 0; nf < 8; ++nf) {
            oacc[nf][0] *= al0; oacc[nf][1] *= al0;
            oacc[nf][2] *= al1; oacc[nf][3] *= al1;
        }

        // ---- O += P V  (m16 x n64 x k128) ----
#pragma unroll
        for (int kb2 = 0; kb2 < 8; ++kb2) {
            uint32_t aph[4], apl[4];
            {
                const float* p0 = s[2 * kb2];
                const float* p1 = s[2 * kb2 + 1];
                __nv_bfloat162 h;
                float rx, ry;
                h = __floats2bfloat162_rn(p0[0], p0[1]);
                rx = p0[0] - __bfloat162float(h.x); ry = p0[1] - __bfloat162float(h.y);
                aph[0] = *(uint32_t*)&h; apl[0] = packbf(rx, ry);
                h = __floats2bfloat162_rn(p0[2], p0[3]);
                rx = p0[2] - __bfloat162float(h.x); ry = p0[3] - __bfloat162float(h.y);
                aph[1] = *(uint32_t*)&h; apl[1] = packbf(rx, ry);
                h = __floats2bfloat162_rn(p1[0], p1[1]);
                rx = p1[0] - __bfloat162float(h.x); ry = p1[1] - __bfloat162float(h.y);
                aph[2] = *(uint32_t*)&h; apl[2] = packbf(rx, ry);
                h = __floats2bfloat162_rn(p1[2], p1[3]);
                rx = p1[2] - __bfloat162float(h.x); ry = p1[3] - __bfloat162float(h.y);
                aph[3] = *(uint32_t*)&h; apl[3] = packbf(rx, ry);
            }
            const uint32_t cofs = (uint32_t)(lhalf + kb2 * 16) * 2;
#pragma unroll
            for (int j2 = 0; j2 < 4; ++j2) {
                uint32_t vh[4], vl[4];
                uint32_t vro = (uint32_t)((j2 * 16 + lrow) * VLD) * 2 + cofs;
                ldsm4(vh, sb + A_VH + vro);
                ldsm4(vl, sb + A_VL + vro);
                mma16816(oacc[2 * j2],     aph, vh[0], vh[2]);
                mma16816(oacc[2 * j2 + 1], aph, vh[1], vh[3]);
                mma16816(oacc[2 * j2],     aph, vl[0], vl[2]);
                mma16816(oacc[2 * j2 + 1], aph, vl[1], vl[3]);
                mma16816(oacc[2 * j2],     apl, vh[0], vh[2]);
                mma16816(oacc[2 * j2 + 1], apl, vh[1], vh[3]);
            }
        }
    }

    // ---- epilogue: normalize + Q residual ----
    const float inv0 = 1.f / l0, inv1 = 1.f / l1;
    const int r0 = q0 + wid * 16 + g;
#pragma unroll
    for (int nf = 0; nf < 8; ++nf) {
        const int d0 = nf * 8 + 2 * t;
        size_t o0 = ((size_t)(b * NQ) + r0) * DM + h * HD + d0;
        size_t o1 = o0 + (size_t)8 * DM;
        float2 q0v = *(const float2*)&Qp[o0];
        float2 q1v = *(const float2*)&Qp[o1];
        *(float2*)&O[o0] = make_float2(fmaf(oacc[nf][0], inv0, q0v.x),
                                       fmaf(oacc[nf][1], inv0, q0v.y));
        *(float2*)&O[o1] = make_float2(fmaf(oacc[nf][2], inv1, q1v.x),
                                       fmaf(oacc[nf][3], inv1, q1v.y));
    }
}

// ===========================================================================
// LayerNorm (warp per row). EMIT=1 additionally writes bf16 hi/lo split.
// ===========================================================================
template <int EMIT>
__global__ __launch_bounds__(256) void ln_kernel(
    const float* __restrict__ X, const float* __restrict__ gam,
    const float* __restrict__ bet, float* __restrict__ Y,
    __nv_bfloat16* __restrict__ Yh, __nv_bfloat16* __restrict__ Yl)
{
    const int row = blockIdx.x * 8 + (threadIdx.x >> 5);
    const int lane = threadIdx.x & 31;
    const float* x = X + (size_t)row * DM;

    float v[16];
    float sum = 0.f, ss = 0.f;
#pragma unroll
    for (int i = 0; i < 4; ++i) {
        float4 tv = *(const float4*)(x + i * 128 + lane * 4);
        v[i * 4 + 0] = tv.x; v[i * 4 + 1] = tv.y;
        v[i * 4 + 2] = tv.z; v[i * 4 + 3] = tv.w;
        sum += tv.x + tv.y + tv.z + tv.w;
        ss += tv.x * tv.x + tv.y * tv.y + tv.z * tv.z + tv.w * tv.w;
    }
#pragma unroll
    for (int m = 16; m >= 1; m >>= 1) {
        sum += __shfl_xor_sync(0xffffffffu, sum, m);
        ss += __shfl_xor_sync(0xffffffffu, ss, m);
    }
    const float mean = sum * (1.f / DM);
    const float var = ss * (1.f / DM) - mean * mean;
    const float inv = rsqrtf(var + 1e-5f);

    float* y = Y + (size_t)row * DM;
#pragma unroll
    for (int i = 0; i < 4; ++i) {
        const int col = i * 128 + lane * 4;
        float4 gv = *(const float4*)(gam + col);
        float4 bb = *(const float4*)(bet + col);
        float4 o;
        o.x = (v[i * 4 + 0] - mean) * inv * gv.x + bb.x;
        o.y = (v[i * 4 + 1] - mean) * inv * gv.y + bb.y;
        o.z = (v[i * 4 + 2] - mean) * inv * gv.z + bb.z;
        o.w = (v[i * 4 + 3] - mean) * inv * gv.w + bb.w;
        *(float4*)(y + col) = o;
        if (EMIT) {
            uint32_t h0, l0, h1, l1;
            split_pair(o.x, o.y, h0, l0);
            split_pair(o.z, o.w, h1, l1);
            size_t e = (size_t)row * DM + col;
            *(uint2*)&Yh[e] = make_uint2(h0, h1);
            *(uint2*)&Yl[e] = make_uint2(l0, l1);
        }
    }
}

// ===========================================================================
extern "C" void kernel_launch(void* const* d_in, const int* in_sizes, int n_in,
                              void* d_out, int out_size)
{
    const float* Q  = (const float*)d_in[0];
    const float* K  = (const float*)d_in[1];
    const float* Wq = (const float*)d_in[2];
    const float* bq = (const float*)d_in[3];
    const float* Wk = (const float*)d_in[4];
    const float* bk = (const float*)d_in[5];
    const float* Wv = (const float*)d_in[6];
    const float* bv = (const float*)d_in[7];
    const float* Wo = (const float*)d_in[8];
    const float* bo = (const float*)d_in[9];
    const float* g0 = (const float*)d_in[10];
    const float* b0 = (const float*)d_in[11];
    const float* g1 = (const float*)d_in[12];
    const float* b1 = (const float*)d_in[13];
    float* out = (float*)d_out;

    float *Qp, *Kp, *Vp, *O, *T, *U;
    __nv_bfloat16 *Ah, *Al, *Kbh, *Kbl, *Wth, *Wtl;
    cudaGetSymbolAddress((void**)&Qp, g_Qp);
    cudaGetSymbolAddress((void**)&Kp, g_Kp);
    cudaGetSymbolAddress((void**)&Vp, g_Vp);
    cudaGetSymbolAddress((void**)&O,  g_O);
    cudaGetSymbolAddress((void**)&T,  g_T);
    cudaGetSymbolAddress((void**)&U,  g_U);
    cudaGetSymbolAddress((void**)&Ah, g_Ah);
    cudaGetSymbolAddress((void**)&Al, g_Al);
    cudaGetSymbolAddress((void**)&Kbh, g_Kbh);
    cudaGetSymbolAddress((void**)&Kbl, g_Kbl);
    cudaGetSymbolAddress((void**)&Wth, g_Wth);
    cudaGetSymbolAddress((void**)&Wtl, g_Wtl);

    cudaFuncSetAttribute(attn_mma, cudaFuncAttributeMaxDynamicSharedMemorySize,
                         A_TOTAL);

    const int WSZ = DM * DM;

    // Input splits
    cvt_split<<<1024, 256>>>((const float4*)Q, Ah, Al, TOT / 4);
    cvt_split<<<1024, 256>>>((const float4*)K, Kbh, Kbl, TOT / 4);
    dim3 wtg(16, 16), wtb(32, 8);
    cvt_wt<<<wtg, wtb>>>(Wq, Wth + 0 * WSZ, Wtl + 0 * WSZ);
    cvt_wt<<<wtg, wtb>>>(Wk, Wth + 1 * WSZ, Wtl + 1 * WSZ);
    cvt_wt<<<wtg, wtb>>>(Wv, Wth + 2 * WSZ, Wtl + 2 * WSZ);
    cvt_wt<<<wtg, wtb>>>(Wo, Wth + 3 * WSZ, Wtl + 3 * WSZ);

    dim3 gg(DM / 128, (BT * NQ) / 128);  // (4, 64)

    // Projections
    gemm_mma<0><<<gg, 256>>>(Ah, Al, Wth + 0 * WSZ, Wtl + 0 * WSZ, bq, nullptr, Qp);
    gemm_mma<0><<<gg, 256>>>(Kbh, Kbl, Wth + 1 * WSZ, Wtl + 1 * WSZ, bk, nullptr, Kp);
    gemm_mma<0><<<gg, 256>>>(Kbh, Kbl, Wth + 2 * WSZ, Wtl + 2 * WSZ, bv, nullptr, Vp);

    // Attention + Q residual
    attn_mma<<<dim3(NQ / 128, HEADS, BT), 256, A_TOTAL>>>(Qp, Kp, Vp, O);

    // LN0 (emit bf16 split of T for the MLP GEMM)
    ln_kernel<1><<<(BT * NQ) / 8, 256>>>(O, g0, b0, T, Ah, Al);

    // U = T + relu(T @ Wo + bo)
    gemm_mma<1><<<gg, 256>>>(Ah, Al, Wth + 3 * WSZ, Wtl + 3 * WSZ, bo, T, U);

    // LN1 -> out
    ln_kernel<0><<<(BT * NQ) / 8, 256>>>(U, g1, b1, out, nullptr, nullptr);
}

// round 4
// speedup vs baseline: 1.8207x; 1.0430x over previous
#include <cuda_runtime.h>
#include <cuda_bf16.h>
#include <math.h>
#include <stdint.h>

#define BT 8
#define NQ 1024
#define DM 512
#define HEADS 8
#define HD 64
#define TOT (BT*NQ*DM)

// fp32 scratch
__device__ float g_Qp[TOT];
__device__ float g_O [TOT];
__device__ float g_T [TOT];
__device__ float g_U [TOT];
// bf16 split scratch
__device__ __nv_bfloat16 g_Ah[TOT], g_Al[TOT];     // raw-Q splits, then T splits
__device__ __nv_bfloat16 g_Kbh[TOT], g_Kbl[TOT];   // raw-K splits
__device__ __nv_bfloat16 g_Qh[TOT], g_Ql[TOT];     // projected Q splits
__device__ __nv_bfloat16 g_Kh[TOT], g_Kl[TOT];     // projected K splits
__device__ __nv_bfloat16 g_Vh[TOT], g_Vl[TOT];     // projected V splits
__device__ __nv_bfloat16 g_Wth[4][DM*DM], g_Wtl[4][DM*DM]; // transposed weights

// ===========================================================================
// Helpers
// ===========================================================================
__device__ __forceinline__ uint32_t smem_u32(const void* p) {
    uint32_t a;
    asm("{ .reg .u64 t; cvta.to.shared.u64 t, %1; cvt.u32.u64 %0, t; }"
        : "=r"(a) : "l"(p));
    return a;
}

__device__ __forceinline__ void ldsm4(uint32_t r[4], uint32_t addr) {
    asm volatile("ldmatrix.sync.aligned.m8n8.x4.shared.b16 {%0,%1,%2,%3}, [%4];"
        : "=r"(r[0]), "=r"(r[1]), "=r"(r[2]), "=r"(r[3]) : "r"(addr));
}
__device__ __forceinline__ void ldsm4t(uint32_t r[4], uint32_t addr) {
    asm volatile("ldmatrix.sync.aligned.m8n8.x4.trans.shared.b16 {%0,%1,%2,%3}, [%4];"
        : "=r"(r[0]), "=r"(r[1]), "=r"(r[2]), "=r"(r[3]) : "r"(addr));
}

__device__ __forceinline__ void mma16816(float c[4], const uint32_t a[4],
                                         uint32_t b0, uint32_t b1) {
    asm volatile(
        "mma.sync.aligned.m16n8k16.row.col.f32.bf16.bf16.f32 "
        "{%0,%1,%2,%3}, {%4,%5,%6,%7}, {%8,%9}, {%0,%1,%2,%3};"
        : "+f"(c[0]), "+f"(c[1]), "+f"(c[2]), "+f"(c[3])
        : "r"(a[0]), "r"(a[1]), "r"(a[2]), "r"(a[3]), "r"(b0), "r"(b1));
}

__device__ __forceinline__ uint32_t packbf(float x, float y) {
    __nv_bfloat162 h = __floats2bfloat162_rn(x, y);
    return *reinterpret_cast<uint32_t*>(&h);
}

__device__ __forceinline__ void split_pair(float x, float y,
                                           uint32_t& hi, uint32_t& lo) {
    __nv_bfloat162 h = __floats2bfloat162_rn(x, y);
    float rx = x - __bfloat162float(h.x);
    float ry = y - __bfloat162float(h.y);
    hi = *reinterpret_cast<uint32_t*>(&h);
    lo = packbf(rx, ry);
}

// ===========================================================================
// Split-convert: fp32 -> bf16 hi/lo
// ===========================================================================
__global__ __launch_bounds__(256) void cvt_split(
    const float4* __restrict__ X, __nv_bfloat16* __restrict__ Xh,
    __nv_bfloat16* __restrict__ Xl, int n4)
{
    for (int i = blockIdx.x * blockDim.x + threadIdx.x; i < n4;
         i += gridDim.x * blockDim.x) {
        float4 v = X[i];
        uint32_t h0, l0, h1, l1;
        split_pair(v.x, v.y, h0, l0);
        split_pair(v.z, v.w, h1, l1);
        *(uint2*)&Xh[4 * i] = make_uint2(h0, h1);
        *(uint2*)&Xl[4 * i] = make_uint2(l0, l1);
    }
}

// Weight transpose + split: W[k][n] -> Wt[n][k] bf16 hi/lo
__global__ __launch_bounds__(256) void cvt_wt(
    const float* __restrict__ W, __nv_bfloat16* __restrict__ Wth,
    __nv_bfloat16* __restrict__ Wtl)
{
    __shared__ float tile[32][33];
    const int tx = threadIdx.x, ty = threadIdx.y;  // 32 x 8
    const int kb = blockIdx.y * 32, nb = blockIdx.x * 32;
#pragma unroll
    for (int i = 0; i < 32; i += 8)
        tile[ty + i][tx] = W[(size_t)(kb + ty + i) * DM + nb + tx];
    __syncthreads();
#pragma unroll
    for (int i = 0; i < 32; i += 8) {
        float v = tile[tx][ty + i];
        __nv_bfloat16 h = __float2bfloat16(v);
        size_t o = (size_t)(nb + ty + i) * DM + kb + tx;
        Wth[o] = h;
        Wtl[o] = __float2bfloat16(v - __bfloat162float(h));
    }
}

// ===========================================================================
// mma.sync GEMM: C[8192,512] = A @ W + bias  (MODE1: +relu+resid)
// WF32: write fp32 C.  WSPL: write bf16 hi/lo split of C.
// CTA 128x128, 8 warps (warp tile 32x64), K-chunk 32.
// ===========================================================================
#define GLD 40   // smem row stride (bf16) - conflict-free for ldsm

template <int MODE, int WF32, int WSPL>
__global__ __launch_bounds__(256) void gemm_mma(
    const __nv_bfloat16* __restrict__ Ah, const __nv_bfloat16* __restrict__ Al,
    const __nv_bfloat16* __restrict__ Bh, const __nv_bfloat16* __restrict__ Bl,
    const float* __restrict__ bias, const float* __restrict__ R,
    float* __restrict__ C, __nv_bfloat16* __restrict__ Ch,
    __nv_bfloat16* __restrict__ Cl)
{
    __shared__ __nv_bfloat16 sAh[128 * GLD], sAl[128 * GLD];
    __shared__ __nv_bfloat16 sBh[128 * GLD], sBl[128 * GLD];

    const int tid = threadIdx.x, wid = tid >> 5, lane = tid & 31;
    const int g = lane >> 2, t = lane & 3;
    const int lrow = lane & 15, lhalf = (lane >> 4) << 3;
    const int bm = blockIdx.y * 128, bn = blockIdx.x * 128;
    const int wm = (wid & 3) * 32, wn = (wid >> 2) * 64;

    const uint32_t uAh = smem_u32(sAh), uAl = smem_u32(sAl);
    const uint32_t uBh = smem_u32(sBh), uBl = smem_u32(sBl);

    const int r = tid >> 1, sgc = (tid & 1) * 16;

    float acc[2][8][4] = {};

    for (int k0 = 0; k0 < DM; k0 += 32) {
        __syncthreads();
#pragma unroll
        for (int c = 0; c < 4; ++c) {
            int col = sgc + c * 4;
            *(uint2*)&sAh[r * GLD + col] = *(const uint2*)&Ah[(size_t)(bm + r) * DM + k0 + col];
            *(uint2*)&sAl[r * GLD + col] = *(const uint2*)&Al[(size_t)(bm + r) * DM + k0 + col];
            *(uint2*)&sBh[r * GLD + col] = *(const uint2*)&Bh[(size_t)(bn + r) * DM + k0 + col];
            *(uint2*)&sBl[r * GLD + col] = *(const uint2*)&Bl[(size_t)(bn + r) * DM + k0 + col];
        }
        __syncthreads();

#pragma unroll
        for (int kb = 0; kb < 2; ++kb) {
            const uint32_t cofs = (uint32_t)(lhalf + kb * 16) * 2;
            uint32_t ah[2][4], al[2][4];
#pragma unroll
            for (int mf = 0; mf < 2; ++mf) {
                uint32_t rofs = (uint32_t)((wm + mf * 16 + lrow) * GLD) * 2 + cofs;
                ldsm4(ah[mf], uAh + rofs);
                ldsm4(al[mf], uAl + rofs);
            }
#pragma unroll
            for (int j = 0; j < 4; ++j) {
                uint32_t bhf[4], blf[4];
                uint32_t rofs = (uint32_t)((wn + j * 16 + lrow) * GLD) * 2 + cofs;
                ldsm4(bhf, uBh + rofs);
                ldsm4(blf, uBl + rofs);
#pragma unroll
                for (int mf = 0; mf < 2; ++mf) {
                    mma16816(acc[mf][2 * j],     ah[mf], bhf[0], bhf[2]);
                    mma16816(acc[mf][2 * j + 1], ah[mf], bhf[1], bhf[3]);
                    mma16816(acc[mf][2 * j],     ah[mf], blf[0], blf[2]);
                    mma16816(acc[mf][2 * j + 1], ah[mf], blf[1], blf[3]);
                    mma16816(acc[mf][2 * j],     al[mf], bhf[0], bhf[2]);
                    mma16816(acc[mf][2 * j + 1], al[mf], bhf[1], bhf[3]);
                }
            }
        }
    }

    // Epilogue
#pragma unroll
    for (int mf = 0; mf < 2; ++mf) {
#pragma unroll
        for (int nf = 0; nf < 8; ++nf) {
            const int row0 = bm + wm + mf * 16 + g;
            const int col = bn + wn + nf * 8 + 2 * t;
            float2 bv = *(const float2*)&bias[col];
            float v0 = acc[mf][nf][0] + bv.x, v1 = acc[mf][nf][1] + bv.y;
            float v2 = acc[mf][nf][2] + bv.x, v3 = acc[mf][nf][3] + bv.y;
            size_t o0 = (size_t)row0 * DM + col;
            size_t o1 = (size_t)(row0 + 8) * DM + col;
            if (MODE == 1) {
                float2 r0 = *(const float2*)&R[o0];
                float2 r1 = *(const float2*)&R[o1];
                v0 = r0.x + fmaxf(v0, 0.f); v1 = r0.y + fmaxf(v1, 0.f);
                v2 = r1.x + fmaxf(v2, 0.f); v3 = r1.y + fmaxf(v3, 0.f);
            }
            if (WF32) {
                *(float2*)&C[o0] = make_float2(v0, v1);
                *(float2*)&C[o1] = make_float2(v2, v3);
            }
            if (WSPL) {
                uint32_t h, l;
                split_pair(v0, v1, h, l);
                *(uint32_t*)&Ch[o0] = h; *(uint32_t*)&Cl[o0] = l;
                split_pair(v2, v3, h, l);
                *(uint32_t*)&Ch[o1] = h; *(uint32_t*)&Cl[o1] = l;
            }
        }
    }
}

// ===========================================================================
// Attention (FA2-style, mma.sync): CTA = 128 q-rows x (head, batch).
// All operands pre-split bf16. Q/K/V smem [row][64] pad 72.
// V fragments via ldmatrix.trans (no transpose needed anywhere).
// ===========================================================================
#define QKLD 72
#define TSZ (128 * QKLD * 2)    // 18432 bytes per tile
#define A_QH 0
#define A_QL (1 * TSZ)
#define A_KH (2 * TSZ)
#define A_KL (3 * TSZ)
#define A_VH (4 * TSZ)
#define A_VL (5 * TSZ)
#define A_TOTAL (6 * TSZ)       // 110592

__global__ __launch_bounds__(256) void attn_mma(
    const float* __restrict__ Qp,
    const __nv_bfloat16* __restrict__ Qh, const __nv_bfloat16* __restrict__ Ql,
    const __nv_bfloat16* __restrict__ Kh, const __nv_bfloat16* __restrict__ Kl,
    const __nv_bfloat16* __restrict__ Vh, const __nv_bfloat16* __restrict__ Vl,
    float* __restrict__ O)
{
    extern __shared__ char sm[];
    const uint32_t sb = smem_u32(sm);
    const int tid = threadIdx.x, wid = tid >> 5, lane = tid & 31;
    const int g = lane >> 2, t = lane & 3;
    const int lrow = lane & 15, lhalf = (lane >> 4) << 3;
    const int b = blockIdx.z, h = blockIdx.y, q0 = blockIdx.x * 128;

    // ---- load Q tile (128 x 64 bf16 hi/lo) ----
    for (int idx = tid; idx < 1024; idx += 256) {
        int r = idx >> 3, s8 = (idx & 7) * 8;
        size_t go = ((size_t)(b * NQ) + q0 + r) * DM + h * HD + s8;
        int e = (r * QKLD + s8) * 2;
        *(uint4*)(sm + A_QH + e) = *(const uint4*)&Qh[go];
        *(uint4*)(sm + A_QL + e) = *(const uint4*)&Ql[go];
    }

    float m0 = -1e30f, m1 = -1e30f, l0 = 0.f, l1 = 0.f;
    float oacc[8][4] = {};
    float s[16][4];

    for (int kc = 0; kc < 8; ++kc) {
        __syncthreads();
        for (int idx = tid; idx < 1024; idx += 256) {
            int r = idx >> 3, s8 = (idx & 7) * 8;
            size_t go = ((size_t)(b * NQ) + kc * 128 + r) * DM + h * HD + s8;
            int e = (r * QKLD + s8) * 2;
            *(uint4*)(sm + A_KH + e) = *(const uint4*)&Kh[go];
            *(uint4*)(sm + A_KL + e) = *(const uint4*)&Kl[go];
            *(uint4*)(sm + A_VH + e) = *(const uint4*)&Vh[go];
            *(uint4*)(sm + A_VL + e) = *(const uint4*)&Vl[go];
        }
        __syncthreads();

        // ---- S = Q K^T  (m16 x n128 x k64 per warp) ----
#pragma unroll
        for (int nf = 0; nf < 16; ++nf)
#pragma unroll
            for (int e = 0; e < 4; ++e) s[nf][e] = 0.f;

#pragma unroll
        for (int kb = 0; kb < 4; ++kb) {
            const uint32_t cofs = (uint32_t)(lhalf + kb * 16) * 2;
            uint32_t aqh[4], aql[4];
            uint32_t qro = (uint32_t)((wid * 16 + lrow) * QKLD) * 2 + cofs;
            ldsm4(aqh, sb + A_QH + qro);
            ldsm4(aql, sb + A_QL + qro);
#pragma unroll
            for (int j = 0; j < 8; ++j) {
                uint32_t bh[4], bl[4];
                uint32_t kro = (uint32_t)((j * 16 + lrow) * QKLD) * 2 + cofs;
                ldsm4(bh, sb + A_KH + kro);
                ldsm4(bl, sb + A_KL + kro);
                mma16816(s[2 * j],     aqh, bh[0], bh[2]);
                mma16816(s[2 * j + 1], aqh, bh[1], bh[3]);
                mma16816(s[2 * j],     aqh, bl[0], bl[2]);
                mma16816(s[2 * j + 1], aqh, bl[1], bl[3]);
                mma16816(s[2 * j],     aql, bh[0], bh[2]);
                mma16816(s[2 * j + 1], aql, bh[1], bh[3]);
            }
        }

        // ---- online softmax (rows g and g+8; 4-lane groups) ----
        const float scale = 0.125f;
        float rm0 = -1e30f, rm1 = -1e30f;
#pragma unroll
        for (int nf = 0; nf < 16; ++nf) {
            rm0 = fmaxf(rm0, fmaxf(s[nf][0], s[nf][1]));
            rm1 = fmaxf(rm1, fmaxf(s[nf][2], s[nf][3]));
        }
        rm0 = fmaxf(rm0, __shfl_xor_sync(0xffffffffu, rm0, 1));
        rm0 = fmaxf(rm0, __shfl_xor_sync(0xffffffffu, rm0, 2));
        rm1 = fmaxf(rm1, __shfl_xor_sync(0xffffffffu, rm1, 1));
        rm1 = fmaxf(rm1, __shfl_xor_sync(0xffffffffu, rm1, 2));
        float mn0 = fmaxf(m0, rm0 * scale);
        float mn1 = fmaxf(m1, rm1 * scale);
        float al0 = __expf(m0 - mn0);
        float al1 = __expf(m1 - mn1);
        float sum0 = 0.f, sum1 = 0.f;
#pragma unroll
        for (int nf = 0; nf < 16; ++nf) {
            s[nf][0] = __expf(fmaf(s[nf][0], scale, -mn0));
            s[nf][1] = __expf(fmaf(s[nf][1], scale, -mn0));
            s[nf][2] = __expf(fmaf(s[nf][2], scale, -mn1));
            s[nf][3] = __expf(fmaf(s[nf][3], scale, -mn1));
            sum0 += s[nf][0] + s[nf][1];
            sum1 += s[nf][2] + s[nf][3];
        }
        sum0 += __shfl_xor_sync(0xffffffffu, sum0, 1);
        sum0 += __shfl_xor_sync(0xffffffffu, sum0, 2);
        sum1 += __shfl_xor_sync(0xffffffffu, sum1, 1);
        sum1 += __shfl_xor_sync(0xffffffffu, sum1, 2);
        l0 = l0 * al0 + sum0;
        l1 = l1 * al1 + sum1;
        m0 = mn0; m1 = mn1;
#pragma unroll
        for (int nf = 0; nf < 8; ++nf) {
            oacc[nf][0] *= al0; oacc[nf][1] *= al0;
            oacc[nf][2] *= al1; oacc[nf][3] *= al1;
        }

        // ---- O += P V  (m16 x n64 x k128), V frags via ldmatrix.trans ----
#pragma unroll
        for (int kb2 = 0; kb2 < 8; ++kb2) {
            uint32_t aph[4], apl[4];
            {
                const float* p0 = s[2 * kb2];
                const float* p1 = s[2 * kb2 + 1];
                split_pair(p0[0], p0[1], aph[0], apl[0]);
                split_pair(p0[2], p0[3], aph[1], apl[1]);
                split_pair(p1[0], p1[1], aph[2], apl[2]);
                split_pair(p1[2], p1[3], aph[3], apl[3]);
            }
#pragma unroll
            for (int j2 = 0; j2 < 4; ++j2) {
                uint32_t vh[4], vl[4];
                // trans ldmatrix from V[k][d]: rows k = kb2*16 + (lane&15),
                // col d = j2*16 + ((lane>>4)<<3)
                uint32_t vro = (uint32_t)(((kb2 * 16 + lrow) * QKLD) +
                                          j2 * 16 + lhalf) * 2;
                ldsm4t(vh, sb + A_VH + vro);
                ldsm4t(vl, sb + A_VL + vro);
                mma16816(oacc[2 * j2],     aph, vh[0], vh[1]);
                mma16816(oacc[2 * j2 + 1], aph, vh[2], vh[3]);
                mma16816(oacc[2 * j2],     aph, vl[0], vl[1]);
                mma16816(oacc[2 * j2 + 1], aph, vl[2], vl[3]);
                mma16816(oacc[2 * j2],     apl, vh[0], vh[1]);
                mma16816(oacc[2 * j2 + 1], apl, vh[2], vh[3]);
            }
        }
    }

    // ---- epilogue: normalize + Q residual ----
    const float inv0 = 1.f / l0, inv1 = 1.f / l1;
    const int r0 = q0 + wid * 16 + g;
#pragma unroll
    for (int nf = 0; nf < 8; ++nf) {
        const int d0 = nf * 8 + 2 * t;
        size_t o0 = ((size_t)(b * NQ) + r0) * DM + h * HD + d0;
        size_t o1 = o0 + (size_t)8 * DM;
        float2 q0v = *(const float2*)&Qp[o0];
        float2 q1v = *(const float2*)&Qp[o1];
        *(float2*)&O[o0] = make_float2(fmaf(oacc[nf][0], inv0, q0v.x),
                                       fmaf(oacc[nf][1], inv0, q0v.y));
        *(float2*)&O[o1] = make_float2(fmaf(oacc[nf][2], inv1, q1v.x),
                                       fmaf(oacc[nf][3], inv1, q1v.y));
    }
}

// ===========================================================================
// LayerNorm (warp per row). EMIT=1 additionally writes bf16 hi/lo split.
// ===========================================================================
template <int EMIT>
__global__ __launch_bounds__(256) void ln_kernel(
    const float* __restrict__ X, const float* __restrict__ gam,
    const float* __restrict__ bet, float* __restrict__ Y,
    __nv_bfloat16* __restrict__ Yh, __nv_bfloat16* __restrict__ Yl)
{
    const int row = blockIdx.x * 8 + (threadIdx.x >> 5);
    const int lane = threadIdx.x & 31;
    const float* x = X + (size_t)row * DM;

    float v[16];
    float sum = 0.f, ss = 0.f;
#pragma unroll
    for (int i = 0; i < 4; ++i) {
        float4 tv = *(const float4*)(x + i * 128 + lane * 4);
        v[i * 4 + 0] = tv.x; v[i * 4 + 1] = tv.y;
        v[i * 4 + 2] = tv.z; v[i * 4 + 3] = tv.w;
        sum += tv.x + tv.y + tv.z + tv.w;
        ss += tv.x * tv.x + tv.y * tv.y + tv.z * tv.z + tv.w * tv.w;
    }
#pragma unroll
    for (int m = 16; m >= 1; m >>= 1) {
        sum += __shfl_xor_sync(0xffffffffu, sum, m);
        ss += __shfl_xor_sync(0xffffffffu, ss, m);
    }
    const float mean = sum * (1.f / DM);
    const float var = ss * (1.f / DM) - mean * mean;
    const float inv = rsqrtf(var + 1e-5f);

    float* y = Y + (size_t)row * DM;
#pragma unroll
    for (int i = 0; i < 4; ++i) {
        const int col = i * 128 + lane * 4;
        float4 gv = *(const float4*)(gam + col);
        float4 bb = *(const float4*)(bet + col);
        float4 o;
        o.x = (v[i * 4 + 0] - mean) * inv * gv.x + bb.x;
        o.y = (v[i * 4 + 1] - mean) * inv * gv.y + bb.y;
        o.z = (v[i * 4 + 2] - mean) * inv * gv.z + bb.z;
        o.w = (v[i * 4 + 3] - mean) * inv * gv.w + bb.w;
        *(float4*)(y + col) = o;
        if (EMIT) {
            uint32_t h0, l0, h1, l1;
            split_pair(o.x, o.y, h0, l0);
            split_pair(o.z, o.w, h1, l1);
            size_t e = (size_t)row * DM + col;
            *(uint2*)&Yh[e] = make_uint2(h0, h1);
            *(uint2*)&Yl[e] = make_uint2(l0, l1);
        }
    }
}

// ===========================================================================
extern "C" void kernel_launch(void* const* d_in, const int* in_sizes, int n_in,
                              void* d_out, int out_size)
{
    const float* Q  = (const float*)d_in[0];
    const float* K  = (const float*)d_in[1];
    const float* Wq = (const float*)d_in[2];
    const float* bq = (const float*)d_in[3];
    const float* Wk = (const float*)d_in[4];
    const float* bk = (const float*)d_in[5];
    const float* Wv = (const float*)d_in[6];
    const float* bv = (const float*)d_in[7];
    const float* Wo = (const float*)d_in[8];
    const float* bo = (const float*)d_in[9];
    const float* g0 = (const float*)d_in[10];
    const float* b0 = (const float*)d_in[11];
    const float* g1 = (const float*)d_in[12];
    const float* b1 = (const float*)d_in[13];
    float* out = (float*)d_out;

    float *Qp, *O, *T, *U;
    __nv_bfloat16 *Ah, *Al, *Kbh, *Kbl, *Qh, *Ql, *Kh, *Kl, *Vh, *Vl, *Wth, *Wtl;
    cudaGetSymbolAddress((void**)&Qp, g_Qp);
    cudaGetSymbolAddress((void**)&O,  g_O);
    cudaGetSymbolAddress((void**)&T,  g_T);
    cudaGetSymbolAddress((void**)&U,  g_U);
    cudaGetSymbolAddress((void**)&Ah, g_Ah);
    cudaGetSymbolAddress((void**)&Al, g_Al);
    cudaGetSymbolAddress((void**)&Kbh, g_Kbh);
    cudaGetSymbolAddress((void**)&Kbl, g_Kbl);
    cudaGetSymbolAddress((void**)&Qh, g_Qh);
    cudaGetSymbolAddress((void**)&Ql, g_Ql);
    cudaGetSymbolAddress((void**)&Kh, g_Kh);
    cudaGetSymbolAddress((void**)&Kl, g_Kl);
    cudaGetSymbolAddress((void**)&Vh, g_Vh);
    cudaGetSymbolAddress((void**)&Vl, g_Vl);
    cudaGetSymbolAddress((void**)&Wth, g_Wth);
    cudaGetSymbolAddress((void**)&Wtl, g_Wtl);

    cudaFuncSetAttribute(attn_mma, cudaFuncAttributeMaxDynamicSharedMemorySize,
                         A_TOTAL);

    const int WSZ = DM * DM;

    // Input splits
    cvt_split<<<1024, 256>>>((const float4*)Q, Ah, Al, TOT / 4);
    cvt_split<<<1024, 256>>>((const float4*)K, Kbh, Kbl, TOT / 4);
    dim3 wtg(16, 16), wtb(32, 8);
    cvt_wt<<<wtg, wtb>>>(Wq, Wth + 0 * WSZ, Wtl + 0 * WSZ);
    cvt_wt<<<wtg, wtb>>>(Wk, Wth + 1 * WSZ, Wtl + 1 * WSZ);
    cvt_wt<<<wtg, wtb>>>(Wv, Wth + 2 * WSZ, Wtl + 2 * WSZ);
    cvt_wt<<<wtg, wtb>>>(Wo, Wth + 3 * WSZ, Wtl + 3 * WSZ);

    dim3 gg(DM / 128, (BT * NQ) / 128);  // (4, 64)

    // Projections (epilogues emit bf16 splits for attention)
    gemm_mma<0,1,1><<<gg, 256>>>(Ah, Al, Wth + 0*WSZ, Wtl + 0*WSZ, bq, nullptr,
                                 Qp, Qh, Ql);
    gemm_mma<0,0,1><<<gg, 256>>>(Kbh, Kbl, Wth + 1*WSZ, Wtl + 1*WSZ, bk, nullptr,
                                 nullptr, Kh, Kl);
    gemm_mma<0,0,1><<<gg, 256>>>(Kbh, Kbl, Wth + 2*WSZ, Wtl + 2*WSZ, bv, nullptr,
                                 nullptr, Vh, Vl);

    // Attention + Q residual
    attn_mma<<<dim3(NQ / 128, HEADS, BT), 256, A_TOTAL>>>(Qp, Qh, Ql, Kh, Kl,
                                                          Vh, Vl, O);

    // LN0 (emit bf16 split of T for the MLP GEMM)
    ln_kernel<1><<<(BT * NQ) / 8, 256>>>(O, g0, b0, T, Ah, Al);

    // U = T + relu(T @ Wo + bo)
    gemm_mma<1,1,0><<<gg, 256>>>(Ah, Al, Wth + 3*WSZ, Wtl + 3*WSZ, bo, T,
                                 U, nullptr, nullptr);

    // LN1 -> out
    ln_kernel<0><<<(BT * NQ) / 8, 256>>>(U, g1, b1, out, nullptr, nullptr);
}

// round 6
// speedup vs baseline: 2.7353x; 1.5023x over previous
#include <cuda_runtime.h>
#include <cuda_bf16.h>
#include <math.h>
#include <stdint.h>

#define BT 8
#define NQ 1024
#define DM 512
#define HEADS 8
#define HD 64
#define TOT (BT*NQ*DM)

// fp32 scratch
__device__ float g_Qp[TOT];
__device__ float g_O [TOT];
__device__ float g_T [TOT];
__device__ float g_U [TOT];
// bf16 split scratch
__device__ __nv_bfloat16 g_Ah[TOT], g_Al[TOT];     // raw-Q splits, then T splits
__device__ __nv_bfloat16 g_Kbh[TOT], g_Kbl[TOT];   // raw-K splits
__device__ __nv_bfloat16 g_Qh[TOT], g_Ql[TOT];     // projected Q splits
__device__ __nv_bfloat16 g_Kh[TOT], g_Kl[TOT];     // projected K splits
__device__ __nv_bfloat16 g_Vh[TOT], g_Vl[TOT];     // projected V splits
__device__ __nv_bfloat16 g_Wth[4][DM*DM], g_Wtl[4][DM*DM]; // transposed weights

// ===========================================================================
// Helpers
// ===========================================================================
__device__ __forceinline__ uint32_t smem_u32(const void* p) {
    uint32_t a;
    asm("{ .reg .u64 t; cvta.to.shared.u64 t, %1; cvt.u32.u64 %0, t; }"
        : "=r"(a) : "l"(p));
    return a;
}

__device__ __forceinline__ void ldsm4(uint32_t r[4], uint32_t addr) {
    asm volatile("ldmatrix.sync.aligned.m8n8.x4.shared.b16 {%0,%1,%2,%3}, [%4];"
        : "=r"(r[0]), "=r"(r[1]), "=r"(r[2]), "=r"(r[3]) : "r"(addr));
}
__device__ __forceinline__ void ldsm4t(uint32_t r[4], uint32_t addr) {
    asm volatile("ldmatrix.sync.aligned.m8n8.x4.trans.shared.b16 {%0,%1,%2,%3}, [%4];"
        : "=r"(r[0]), "=r"(r[1]), "=r"(r[2]), "=r"(r[3]) : "r"(addr));
}

__device__ __forceinline__ void mma16816(float c[4], const uint32_t a[4],
                                         uint32_t b0, uint32_t b1) {
    asm volatile(
        "mma.sync.aligned.m16n8k16.row.col.f32.bf16.bf16.f32 "
        "{%0,%1,%2,%3}, {%4,%5,%6,%7}, {%8,%9}, {%0,%1,%2,%3};"
        : "+f"(c[0]), "+f"(c[1]), "+f"(c[2]), "+f"(c[3])
        : "r"(a[0]), "r"(a[1]), "r"(a[2]), "r"(a[3]), "r"(b0), "r"(b1));
}

__device__ __forceinline__ uint32_t packbf(float x, float y) {
    __nv_bfloat162 h = __floats2bfloat162_rn(x, y);
    return *reinterpret_cast<uint32_t*>(&h);
}

__device__ __forceinline__ void split_pair(float x, float y,
                                           uint32_t& hi, uint32_t& lo) {
    __nv_bfloat162 h = __floats2bfloat162_rn(x, y);
    float rx = x - __bfloat162float(h.x);
    float ry = y - __bfloat162float(h.y);
    hi = *reinterpret_cast<uint32_t*>(&h);
    lo = packbf(rx, ry);
}

__device__ __forceinline__ void cpa16(uint32_t dst, const void* src) {
    asm volatile("cp.async.ca.shared.global [%0], [%1], 16;"
                 :: "r"(dst), "l"(src));
}
#define CP_COMMIT() asm volatile("cp.async.commit_group;" ::: "memory")
#define CP_WAIT0()  asm volatile("cp.async.wait_group 0;" ::: "memory")
#define CP_WAIT1()  asm volatile("cp.async.wait_group 1;" ::: "memory")

// ===========================================================================
// Split-convert: fp32 -> bf16 hi/lo
// ===========================================================================
__global__ __launch_bounds__(256) void cvt_split(
    const float4* __restrict__ X, __nv_bfloat16* __restrict__ Xh,
    __nv_bfloat16* __restrict__ Xl, int n4)
{
    for (int i = blockIdx.x * blockDim.x + threadIdx.x; i < n4;
         i += gridDim.x * blockDim.x) {
        float4 v = X[i];
        uint32_t h0, l0, h1, l1;
        split_pair(v.x, v.y, h0, l0);
        split_pair(v.z, v.w, h1, l1);
        *(uint2*)&Xh[4 * i] = make_uint2(h0, h1);
        *(uint2*)&Xl[4 * i] = make_uint2(l0, l1);
    }
}

// Weight transpose + split: W[k][n] -> Wt[n][k] bf16 hi/lo
__global__ __launch_bounds__(256) void cvt_wt(
    const float* __restrict__ W, __nv_bfloat16* __restrict__ Wth,
    __nv_bfloat16* __restrict__ Wtl)
{
    __shared__ float tile[32][33];
    const int tx = threadIdx.x, ty = threadIdx.y;  // 32 x 8
    const int kb = blockIdx.y * 32, nb = blockIdx.x * 32;
#pragma unroll
    for (int i = 0; i < 32; i += 8)
        tile[ty + i][tx] = W[(size_t)(kb + ty + i) * DM + nb + tx];
    __syncthreads();
#pragma unroll
    for (int i = 0; i < 32; i += 8) {
        float v = tile[tx][ty + i];
        __nv_bfloat16 h = __float2bfloat16(v);
        size_t o = (size_t)(nb + ty + i) * DM + kb + tx;
        Wth[o] = h;
        Wtl[o] = __float2bfloat16(v - __bfloat162float(h));
    }
}

// ===========================================================================
// mma.sync GEMM, cp.async 2-stage pipelined.
// C[8192,512] = A @ W + bias  (MODE1: +relu+resid)
// CTA 128x128, 8 warps (warp tile 32x64), K-chunk 32.
// ===========================================================================
#define GLD 40                 // smem row stride (bf16)
#define GSTG (128 * GLD)       // elems per array per stage
#define G_SMEM (2 * 4 * GSTG * 2)   // bytes = 81920

template <int MODE, int WF32, int WSPL>
__global__ __launch_bounds__(256, 2) void gemm_mma(
    const __nv_bfloat16* __restrict__ Ah, const __nv_bfloat16* __restrict__ Al,
    const __nv_bfloat16* __restrict__ Bh, const __nv_bfloat16* __restrict__ Bl,
    const float* __restrict__ bias, const float* __restrict__ R,
    float* __restrict__ C, __nv_bfloat16* __restrict__ Ch,
    __nv_bfloat16* __restrict__ Cl)
{
    extern __shared__ __nv_bfloat16 gsm[];
    const uint32_t base = smem_u32(gsm);

    const int tid = threadIdx.x, wid = tid >> 5, lane = tid & 31;
    const int g = lane >> 2, t = lane & 3;
    const int lrow = lane & 15, lhalf = (lane >> 4) << 3;
    const int bm = blockIdx.y * 128, bn = blockIdx.x * 128;
    const int wm = (wid & 3) * 32, wn = (wid >> 2) * 64;

    // load mapping: 512 16B-chunks per array; 2 per thread
    const int cid0 = tid * 2;
    const int lr0 = cid0 >> 2, ls0 = (cid0 & 3) * 8;
    const int lr1 = lr0, ls1 = ls0 + 8;   // cid0+1 same row, next seg

    float acc[2][8][4] = {};

    // prologue: issue chunk 0
    {
        uint32_t so = base;
        size_t ga0 = (size_t)(bm + lr0) * DM + ls0;
        size_t gb0 = (size_t)(bn + lr0) * DM + ls0;
        uint32_t o0 = (uint32_t)(lr0 * GLD + ls0) * 2;
        uint32_t o1 = (uint32_t)(lr1 * GLD + ls1) * 2;
        cpa16(so + o0, Ah + ga0);            cpa16(so + o1, Ah + ga0 + 8);
        cpa16(so + GSTG*2 + o0, Al + ga0);   cpa16(so + GSTG*2 + o1, Al + ga0 + 8);
        cpa16(so + 2*GSTG*2 + o0, Bh + gb0); cpa16(so + 2*GSTG*2 + o1, Bh + gb0 + 8);
        cpa16(so + 3*GSTG*2 + o0, Bl + gb0); cpa16(so + 3*GSTG*2 + o1, Bl + gb0 + 8);
        CP_COMMIT();
    }

    for (int c = 0; c < 16; ++c) {
        if (c + 1 < 16) {
            const int k0 = (c + 1) * 32;
            uint32_t so = base + ((c + 1) & 1) * (4 * GSTG * 2);
            size_t ga0 = (size_t)(bm + lr0) * DM + k0 + ls0;
            size_t gb0 = (size_t)(bn + lr0) * DM + k0 + ls0;
            uint32_t o0 = (uint32_t)(lr0 * GLD + ls0) * 2;
            uint32_t o1 = (uint32_t)(lr1 * GLD + ls1) * 2;
            cpa16(so + o0, Ah + ga0);            cpa16(so + o1, Ah + ga0 + 8);
            cpa16(so + GSTG*2 + o0, Al + ga0);   cpa16(so + GSTG*2 + o1, Al + ga0 + 8);
            cpa16(so + 2*GSTG*2 + o0, Bh + gb0); cpa16(so + 2*GSTG*2 + o1, Bh + gb0 + 8);
            cpa16(so + 3*GSTG*2 + o0, Bl + gb0); cpa16(so + 3*GSTG*2 + o1, Bl + gb0 + 8);
            CP_COMMIT();
            CP_WAIT1();
        } else {
            CP_WAIT0();
        }
        __syncthreads();

        const uint32_t uS = base + (c & 1) * (4 * GSTG * 2);
        const uint32_t uAh = uS, uAl = uS + GSTG*2;
        const uint32_t uBh = uS + 2*GSTG*2, uBl = uS + 3*GSTG*2;

#pragma unroll
        for (int kb = 0; kb < 2; ++kb) {
            const uint32_t cofs = (uint32_t)(lhalf + kb * 16) * 2;
            uint32_t ah[2][4], al[2][4];
#pragma unroll
            for (int mf = 0; mf < 2; ++mf) {
                uint32_t rofs = (uint32_t)((wm + mf * 16 + lrow) * GLD) * 2 + cofs;
                ldsm4(ah[mf], uAh + rofs);
                ldsm4(al[mf], uAl + rofs);
            }
#pragma unroll
            for (int j = 0; j < 4; ++j) {
                uint32_t bhf[4], blf[4];
                uint32_t rofs = (uint32_t)((wn + j * 16 + lrow) * GLD) * 2 + cofs;
                ldsm4(bhf, uBh + rofs);
                ldsm4(blf, uBl + rofs);
#pragma unroll
                for (int mf = 0; mf < 2; ++mf) {
                    mma16816(acc[mf][2 * j],     ah[mf], bhf[0], bhf[2]);
                    mma16816(acc[mf][2 * j + 1], ah[mf], bhf[1], bhf[3]);
                    mma16816(acc[mf][2 * j],     ah[mf], blf[0], blf[2]);
                    mma16816(acc[mf][2 * j + 1], ah[mf], blf[1], blf[3]);
                    mma16816(acc[mf][2 * j],     al[mf], bhf[0], bhf[2]);
                    mma16816(acc[mf][2 * j + 1], al[mf], bhf[1], bhf[3]);
                }
            }
        }
        __syncthreads();   // stage consumed before next overwrite
    }

    // Epilogue
#pragma unroll
    for (int mf = 0; mf < 2; ++mf) {
#pragma unroll
        for (int nf = 0; nf < 8; ++nf) {
            const int row0 = bm + wm + mf * 16 + g;
            const int col = bn + wn + nf * 8 + 2 * t;
            float2 bv = *(const float2*)&bias[col];
            float v0 = acc[mf][nf][0] + bv.x, v1 = acc[mf][nf][1] + bv.y;
            float v2 = acc[mf][nf][2] + bv.x, v3 = acc[mf][nf][3] + bv.y;
            size_t o0 = (size_t)row0 * DM + col;
            size_t o1 = (size_t)(row0 + 8) * DM + col;
            if (MODE == 1) {
                float2 r0 = *(const float2*)&R[o0];
                float2 r1 = *(const float2*)&R[o1];
                v0 = r0.x + fmaxf(v0, 0.f); v1 = r0.y + fmaxf(v1, 0.f);
                v2 = r1.x + fmaxf(v2, 0.f); v3 = r1.y + fmaxf(v3, 0.f);
            }
            if (WF32) {
                *(float2*)&C[o0] = make_float2(v0, v1);
                *(float2*)&C[o1] = make_float2(v2, v3);
            }
            if (WSPL) {
                uint32_t h, l;
                split_pair(v0, v1, h, l);
                *(uint32_t*)&Ch[o0] = h; *(uint32_t*)&Cl[o0] = l;
                split_pair(v2, v3, h, l);
                *(uint32_t*)&Ch[o1] = h; *(uint32_t*)&Cl[o1] = l;
            }
        }
    }
}

// ===========================================================================
// Attention: CTA = 128 q-rows x (head, batch); 16 key-chunks of 64,
// cp.async double-buffered K/V; Q fragments register-resident.
// ===========================================================================
#define ATLD 72
#define ATILE (64 * ATLD)          // elems per 64-row tile
#define ASTG  (4 * ATILE)          // elems per stage (KH,KL,VH,VL)
#define A_SMEM (2 * ASTG * 2)      // 73728 bytes

__global__ __launch_bounds__(256, 2) void attn_mma(
    const float* __restrict__ Qp,
    const __nv_bfloat16* __restrict__ Qh, const __nv_bfloat16* __restrict__ Ql,
    const __nv_bfloat16* __restrict__ Kh, const __nv_bfloat16* __restrict__ Kl,
    const __nv_bfloat16* __restrict__ Vh, const __nv_bfloat16* __restrict__ Vl,
    float* __restrict__ O)
{
    extern __shared__ char sm[];
    const uint32_t sb = smem_u32(sm);
    const int tid = threadIdx.x, wid = tid >> 5, lane = tid & 31;
    const int g = lane >> 2, t = lane & 3;
    const int lrow = lane & 15, lhalf = (lane >> 4) << 3;
    const int b = blockIdx.z, h = blockIdx.y, q0 = blockIdx.x * 128;

    // ---- Q prologue: stage Q tile in smem, pull fragments to registers ----
    for (int idx = tid; idx < 1024; idx += 256) {
        int r = idx >> 3, s8 = (idx & 7) * 8;
        size_t go = ((size_t)(b * NQ) + q0 + r) * DM + h * HD + s8;
        int e = (r * ATLD + s8) * 2;
        *(uint4*)(sm + e) = *(const uint4*)&Qh[go];
        *(uint4*)(sm + 128 * ATLD * 2 + e) = *(const uint4*)&Ql[go];
    }
    __syncthreads();
    uint32_t aqh[4][4], aql[4][4];
#pragma unroll
    for (int kb = 0; kb < 4; ++kb) {
        uint32_t qro = (uint32_t)((wid * 16 + lrow) * ATLD) * 2 +
                       (uint32_t)(lhalf + kb * 16) * 2;
        ldsm4(aqh[kb], sb + qro);
        ldsm4(aql[kb], sb + 128 * ATLD * 2 + qro);
    }
    __syncthreads();

    // load mapping for a 64-row chunk: 512 16B-chunks per tile; 2 per thread
    const int cid0 = tid * 2;
    const int lr0 = cid0 >> 3, ls0 = (cid0 & 7) * 8;
    const int ls1 = ls0 + 8;

    float m0 = -1e30f, m1 = -1e30f, l0 = 0.f, l1 = 0.f;
    float oacc[8][4] = {};

    // prologue: issue chunk 0
    {
        uint32_t so = sb;
        size_t go = ((size_t)(b * NQ) + lr0) * DM + h * HD + ls0;
        uint32_t o0 = (uint32_t)(lr0 * ATLD + ls0) * 2;
        uint32_t o1 = (uint32_t)(lr0 * ATLD + ls1) * 2;
        cpa16(so + o0, Kh + go);                cpa16(so + o1, Kh + go + 8);
        cpa16(so + ATILE*2 + o0, Kl + go);      cpa16(so + ATILE*2 + o1, Kl + go + 8);
        cpa16(so + 2*ATILE*2 + o0, Vh + go);    cpa16(so + 2*ATILE*2 + o1, Vh + go + 8);
        cpa16(so + 3*ATILE*2 + o0, Vl + go);    cpa16(so + 3*ATILE*2 + o1, Vl + go + 8);
        CP_COMMIT();
    }

    for (int kc = 0; kc < 16; ++kc) {
        if (kc + 1 < 16) {
            uint32_t so = sb + ((kc + 1) & 1) * (ASTG * 2);
            size_t go = ((size_t)(b * NQ) + (kc + 1) * 64 + lr0) * DM + h * HD + ls0;
            uint32_t o0 = (uint32_t)(lr0 * ATLD + ls0) * 2;
            uint32_t o1 = (uint32_t)(lr0 * ATLD + ls1) * 2;
            cpa16(so + o0, Kh + go);                cpa16(so + o1, Kh + go + 8);
            cpa16(so + ATILE*2 + o0, Kl + go);      cpa16(so + ATILE*2 + o1, Kl + go + 8);
            cpa16(so + 2*ATILE*2 + o0, Vh + go);    cpa16(so + 2*ATILE*2 + o1, Vh + go + 8);
            cpa16(so + 3*ATILE*2 + o0, Vl + go);    cpa16(so + 3*ATILE*2 + o1, Vl + go + 8);
            CP_COMMIT();
            CP_WAIT1();
        } else {
            CP_WAIT0();
        }
        __syncthreads();

        const uint32_t uS = sb + (kc & 1) * (ASTG * 2);
        const uint32_t uKH = uS, uKL = uS + ATILE*2;
        const uint32_t uVH = uS + 2*ATILE*2, uVL = uS + 3*ATILE*2;

        // ---- S = Q K^T (m16 x n64 x k64) ----
        float s[8][4];
#pragma unroll
        for (int nf = 0; nf < 8; ++nf)
#pragma unroll
            for (int e = 0; e < 4; ++e) s[nf][e] = 0.f;

#pragma unroll
        for (int kb = 0; kb < 4; ++kb) {
            const uint32_t cofs = (uint32_t)(lhalf + kb * 16) * 2;
#pragma unroll
            for (int j = 0; j < 4; ++j) {
                uint32_t bh[4], bl[4];
                uint32_t kro = (uint32_t)((j * 16 + lrow) * ATLD) * 2 + cofs;
                ldsm4(bh, uKH + kro);
                ldsm4(bl, uKL + kro);
                mma16816(s[2 * j],     aqh[kb], bh[0], bh[2]);
                mma16816(s[2 * j + 1], aqh[kb], bh[1], bh[3]);
                mma16816(s[2 * j],     aqh[kb], bl[0], bl[2]);
                mma16816(s[2 * j + 1], aqh[kb], bl[1], bl[3]);
                mma16816(s[2 * j],     aql[kb], bh[0], bh[2]);
                mma16816(s[2 * j + 1], aql[kb], bh[1], bh[3]);
            }
        }

        // ---- online softmax (rows g and g+8) ----
        const float scale = 0.125f;
        float rm0 = -1e30f, rm1 = -1e30f;
#pragma unroll
        for (int nf = 0; nf < 8; ++nf) {
            rm0 = fmaxf(rm0, fmaxf(s[nf][0], s[nf][1]));
            rm1 = fmaxf(rm1, fmaxf(s[nf][2], s[nf][3]));
        }
        rm0 = fmaxf(rm0, __shfl_xor_sync(0xffffffffu, rm0, 1));
        rm0 = fmaxf(rm0, __shfl_xor_sync(0xffffffffu, rm0, 2));
        rm1 = fmaxf(rm1, __shfl_xor_sync(0xffffffffu, rm1, 1));
        rm1 = fmaxf(rm1, __shfl_xor_sync(0xffffffffu, rm1, 2));
        float mn0 = fmaxf(m0, rm0 * scale);
        float mn1 = fmaxf(m1, rm1 * scale);
        float al0 = __expf(m0 - mn0);
        float al1 = __expf(m1 - mn1);
        float sum0 = 0.f, sum1 = 0.f;
#pragma unroll
        for (int nf = 0; nf < 8; ++nf) {
            s[nf][0] = __expf(fmaf(s[nf][0], scale, -mn0));
            s[nf][1] = __expf(fmaf(s[nf][1], scale, -mn0));
            s[nf][2] = __expf(fmaf(s[nf][2], scale, -mn1));
            s[nf][3] = __expf(fmaf(s[nf][3], scale, -mn1));
            sum0 += s[nf][0] + s[nf][1];
            sum1 += s[nf][2] + s[nf][3];
        }
        sum0 += __shfl_xor_sync(0xffffffffu, sum0, 1);
        sum0 += __shfl_xor_sync(0xffffffffu, sum0, 2);
        sum1 += __shfl_xor_sync(0xffffffffu, sum1, 1);
        sum1 += __shfl_xor_sync(0xffffffffu, sum1, 2);
        l0 = l0 * al0 + sum0;
        l1 = l1 * al1 + sum1;
        m0 = mn0; m1 = mn1;
#pragma unroll
        for (int nf = 0; nf < 8; ++nf) {
            oacc[nf][0] *= al0; oacc[nf][1] *= al0;
            oacc[nf][2] *= al1; oacc[nf][3] *= al1;
        }

        // ---- O += P V (m16 x n64 x k64), V frags via ldmatrix.trans ----
#pragma unroll
        for (int kb2 = 0; kb2 < 4; ++kb2) {
            uint32_t aph[4], apl[4];
            {
                const float* p0 = s[2 * kb2];
                const float* p1 = s[2 * kb2 + 1];
                split_pair(p0[0], p0[1], aph[0], apl[0]);
                split_pair(p0[2], p0[3], aph[1], apl[1]);
                split_pair(p1[0], p1[1], aph[2], apl[2]);
                split_pair(p1[2], p1[3], aph[3], apl[3]);
            }
#pragma unroll
            for (int j2 = 0; j2 < 4; ++j2) {
                uint32_t vh[4], vl[4];
                uint32_t vro = (uint32_t)(((kb2 * 16 + lrow) * ATLD) +
                                          j2 * 16 + lhalf) * 2;
                ldsm4t(vh, uVH + vro);
                ldsm4t(vl, uVL + vro);
                mma16816(oacc[2 * j2],     aph, vh[0], vh[1]);
                mma16816(oacc[2 * j2 + 1], aph, vh[2], vh[3]);
                mma16816(oacc[2 * j2],     aph, vl[0], vl[1]);
                mma16816(oacc[2 * j2 + 1], aph, vl[2], vl[3]);
                mma16816(oacc[2 * j2],     apl, vh[0], vh[1]);
                mma16816(oacc[2 * j2 + 1], apl, vh[2], vh[3]);
            }
        }
        __syncthreads();   // stage consumed before next overwrite
    }

    // ---- epilogue: normalize + Q residual ----
    const float inv0 = 1.f / l0, inv1 = 1.f / l1;
    const int r0 = q0 + wid * 16 + g;
#pragma unroll
    for (int nf = 0; nf < 8; ++nf) {
        const int d0 = nf * 8 + 2 * t;
        size_t o0 = ((size_t)(b * NQ) + r0) * DM + h * HD + d0;
        size_t o1 = o0 + (size_t)8 * DM;
        float2 q0v = *(const float2*)&Qp[o0];
        float2 q1v = *(const float2*)&Qp[o1];
        *(float2*)&O[o0] = make_float2(fmaf(oacc[nf][0], inv0, q0v.x),
                                       fmaf(oacc[nf][1], inv0, q0v.y));
        *(float2*)&O[o1] = make_float2(fmaf(oacc[nf][2], inv1, q1v.x),
                                       fmaf(oacc[nf][3], inv1, q1v.y));
    }
}

// ===========================================================================
// LayerNorm (warp per row). EMIT=1 additionally writes bf16 hi/lo split.
// ===========================================================================
template <int EMIT>
__global__ __launch_bounds__(256) void ln_kernel(
    const float* __restrict__ X, const float* __restrict__ gam,
    const float* __restrict__ bet, float* __restrict__ Y,
    __nv_bfloat16* __restrict__ Yh, __nv_bfloat16* __restrict__ Yl)
{
    const int row = blockIdx.x * 8 + (threadIdx.x >> 5);
    const int lane = threadIdx.x & 31;
    const float* x = X + (size_t)row * DM;

    float v[16];
    float sum = 0.f, ss = 0.f;
#pragma unroll
    for (int i = 0; i < 4; ++i) {
        float4 tv = *(const float4*)(x + i * 128 + lane * 4);
        v[i * 4 + 0] = tv.x; v[i * 4 + 1] = tv.y;
        v[i * 4 + 2] = tv.z; v[i * 4 + 3] = tv.w;
        sum += tv.x + tv.y + tv.z + tv.w;
        ss += tv.x * tv.x + tv.y * tv.y + tv.z * tv.z + tv.w * tv.w;
    }
#pragma unroll
    for (int m = 16; m >= 1; m >>= 1) {
        sum += __shfl_xor_sync(0xffffffffu, sum, m);
        ss += __shfl_xor_sync(0xffffffffu, ss, m);
    }
    const float mean = sum * (1.f / DM);
    const float var = ss * (1.f / DM) - mean * mean;
    const float inv = rsqrtf(var + 1e-5f);

    float* y = Y + (size_t)row * DM;
#pragma unroll
    for (int i = 0; i < 4; ++i) {
        const int col = i * 128 + lane * 4;
        float4 gv = *(const float4*)(gam + col);
        float4 bb = *(const float4*)(bet + col);
        float4 o;
        o.x = (v[i * 4 + 0] - mean) * inv * gv.x + bb.x;
        o.y = (v[i * 4 + 1] - mean) * inv * gv.y + bb.y;
        o.z = (v[i * 4 + 2] - mean) * inv * gv.z + bb.z;
        o.w = (v[i * 4 + 3] - mean) * inv * gv.w + bb.w;
        *(float4*)(y + col) = o;
        if (EMIT) {
            uint32_t h0, l0, h1, l1;
            split_pair(o.x, o.y, h0, l0);
            split_pair(o.z, o.w, h1, l1);
            size_t e = (size_t)row * DM + col;
            *(uint2*)&Yh[e] = make_uint2(h0, h1);
            *(uint2*)&Yl[e] = make_uint2(l0, l1);
        }
    }
}

// ===========================================================================
extern "C" void kernel_launch(void* const* d_in, const int* in_sizes, int n_in,
                              void* d_out, int out_size)
{
    const float* Q  = (const float*)d_in[0];
    const float* K  = (const float*)d_in[1];
    const float* Wq = (const float*)d_in[2];
    const float* bq = (const float*)d_in[3];
    const float* Wk = (const float*)d_in[4];
    const float* bk = (const float*)d_in[5];
    const float* Wv = (const float*)d_in[6];
    const float* bv = (const float*)d_in[7];
    const float* Wo = (const float*)d_in[8];
    const float* bo = (const float*)d_in[9];
    const float* g0 = (const float*)d_in[10];
    const float* b0 = (const float*)d_in[11];
    const float* g1 = (const float*)d_in[12];
    const float* b1 = (const float*)d_in[13];
    float* out = (float*)d_out;

    float *Qp, *O, *T, *U;
    __nv_bfloat16 *Ah, *Al, *Kbh, *Kbl, *Qh, *Ql, *Kh, *Kl, *Vh, *Vl, *Wth, *Wtl;
    cudaGetSymbolAddress((void**)&Qp, g_Qp);
    cudaGetSymbolAddress((void**)&O,  g_O);
    cudaGetSymbolAddress((void**)&T,  g_T);
    cudaGetSymbolAddress((void**)&U,  g_U);
    cudaGetSymbolAddress((void**)&Ah, g_Ah);
    cudaGetSymbolAddress((void**)&Al, g_Al);
    cudaGetSymbolAddress((void**)&Kbh, g_Kbh);
    cudaGetSymbolAddress((void**)&Kbl, g_Kbl);
    cudaGetSymbolAddress((void**)&Qh, g_Qh);
    cudaGetSymbolAddress((void**)&Ql, g_Ql);
    cudaGetSymbolAddress((void**)&Kh, g_Kh);
    cudaGetSymbolAddress((void**)&Kl, g_Kl);
    cudaGetSymbolAddress((void**)&Vh, g_Vh);
    cudaGetSymbolAddress((void**)&Vl, g_Vl);
    cudaGetSymbolAddress((void**)&Wth, g_Wth);
    cudaGetSymbolAddress((void**)&Wtl, g_Wtl);

    static int attr_set = 0;
    if (!attr_set) {
        cudaFuncSetAttribute(attn_mma,
            cudaFuncAttributeMaxDynamicSharedMemorySize, A_SMEM);
        cudaFuncSetAttribute(gemm_mma<0,1,1>,
            cudaFuncAttributeMaxDynamicSharedMemorySize, G_SMEM);
        cudaFuncSetAttribute(gemm_mma<0,0,1>,
            cudaFuncAttributeMaxDynamicSharedMemorySize, G_SMEM);
        cudaFuncSetAttribute(gemm_mma<1,1,0>,
            cudaFuncAttributeMaxDynamicSharedMemorySize, G_SMEM);
        attr_set = 1;
    }

    const int WSZ = DM * DM;

    // Input splits
    cvt_split<<<1024, 256>>>((const float4*)Q, Ah, Al, TOT / 4);
    cvt_split<<<1024, 256>>>((const float4*)K, Kbh, Kbl, TOT / 4);
    dim3 wtg(16, 16), wtb(32, 8);
    cvt_wt<<<wtg, wtb>>>(Wq, Wth + 0 * WSZ, Wtl + 0 * WSZ);
    cvt_wt<<<wtg, wtb>>>(Wk, Wth + 1 * WSZ, Wtl + 1 * WSZ);
    cvt_wt<<<wtg, wtb>>>(Wv, Wth + 2 * WSZ, Wtl + 2 * WSZ);
    cvt_wt<<<wtg, wtb>>>(Wo, Wth + 3 * WSZ, Wtl + 3 * WSZ);

    dim3 gg(DM / 128, (BT * NQ) / 128);  // (4, 64)

    // Projections (epilogues emit bf16 splits for attention)
    gemm_mma<0,1,1><<<gg, 256, G_SMEM>>>(Ah, Al, Wth + 0*WSZ, Wtl + 0*WSZ, bq,
                                         nullptr, Qp, Qh, Ql);
    gemm_mma<0,0,1><<<gg, 256, G_SMEM>>>(Kbh, Kbl, Wth + 1*WSZ, Wtl + 1*WSZ, bk,
                                         nullptr, nullptr, Kh, Kl);
    gemm_mma<0,0,1><<<gg, 256, G_SMEM>>>(Kbh, Kbl, Wth + 2*WSZ, Wtl + 2*WSZ, bv,
                                         nullptr, nullptr, Vh, Vl);

    // Attention + Q residual
    attn_mma<<<dim3(NQ / 128, HEADS, BT), 256, A_SMEM>>>(Qp, Qh, Ql, Kh, Kl,
                                                         Vh, Vl, O);

    // LN0 (emit bf16 split of T for the MLP GEMM)
    ln_kernel<1><<<(BT * NQ) / 8, 256>>>(O, g0, b0, T, Ah, Al);

    // U = T + relu(T @ Wo + bo)
    gemm_mma<1,1,0><<<gg, 256, G_SMEM>>>(Ah, Al, Wth + 3*WSZ, Wtl + 3*WSZ, bo,
                                         T, U, nullptr, nullptr);

    // LN1 -> out
    ln_kernel<0><<<(BT * NQ) / 8, 256>>>(U, g1, b1, out, nullptr, nullptr);
}